// round 14
// baseline (speedup 1.0000x reference)
#include <cuda_runtime.h>
#include <cuda_fp16.h>
#include <cstdint>
#include <math.h>

#define EMB   768
#define HEADS 8
#define HD    96
#define BATCH 4
#define SEQ   2048
#define BHN   (BATCH*HEADS)
#define MTOT  (BATCH*SEQ)
#define KC2   (2*EMB)        // 1536 (compensated operands: Q, K)
#define LOG2E 1.4426950408889634f

// ---------------- scratch globals (module-load allocated) -------------------
__device__ __half g_Xc[(size_t)MTOT * KC2];    // x split [ah, al]
__device__ __half g_Oc[(size_t)MTOT * EMB];    // attn-out hi-only fp16
__device__ __half g_Wc[4][(size_t)EMB * KC2];  // W^T: Q/K=[bh,bh] str 1536, V/O=[bh] str 768
__device__ __half g_Qh[(size_t)BHN * SEQ * HD];
__device__ __half g_Kh[(size_t)BHN * SEQ * HD];
__device__ __half g_Vh[(size_t)BHN * SEQ * HD];

// ---------------- helpers ---------------------------------------------------
__device__ __forceinline__ uint32_t smem_u32(const void* p) {
    uint32_t a;
    asm("{ .reg .u64 t; cvta.to.shared.u64 t, %1; cvt.u32.u64 %0, t; }" : "=r"(a) : "l"(p));
    return a;
}
__device__ __forceinline__ void cpa16(uint32_t d, const void* s) {
    asm volatile("cp.async.cg.shared.global [%0], [%1], 16;" :: "r"(d), "l"(s));
}
#define CP_COMMIT() asm volatile("cp.async.commit_group;")
#define CP_WAIT0()  asm volatile("cp.async.wait_group 0;")
#define CP_WAIT1()  asm volatile("cp.async.wait_group 1;")

__device__ __forceinline__ void ldm4(uint32_t* r, uint32_t addr) {
    asm volatile("ldmatrix.sync.aligned.m8n8.x4.shared.b16 {%0,%1,%2,%3}, [%4];"
        : "=r"(r[0]), "=r"(r[1]), "=r"(r[2]), "=r"(r[3]) : "r"(addr));
}
__device__ __forceinline__ void ldm4t(uint32_t* r, uint32_t addr) {
    asm volatile("ldmatrix.sync.aligned.m8n8.x4.trans.shared.b16 {%0,%1,%2,%3}, [%4];"
        : "=r"(r[0]), "=r"(r[1]), "=r"(r[2]), "=r"(r[3]) : "r"(addr));
}
__device__ __forceinline__ void mma_f16(float* c, const uint32_t* a, uint32_t b0, uint32_t b1) {
    asm volatile("mma.sync.aligned.m16n8k16.row.col.f32.f16.f16.f32 "
        "{%0,%1,%2,%3}, {%4,%5,%6,%7}, {%8,%9}, {%0,%1,%2,%3};"
        : "+f"(c[0]), "+f"(c[1]), "+f"(c[2]), "+f"(c[3])
        : "r"(a[0]), "r"(a[1]), "r"(a[2]), "r"(a[3]), "r"(b0), "r"(b1));
}
// guaranteed-MUFU exp2
__device__ __forceinline__ float ex2f(float x) {
    float y;
    asm("ex2.approx.ftz.f32 %0, %1;" : "=f"(y) : "f"(x));
    return y;
}
// pack two fp32 -> fp16x2 {lo=x, hi=y} in one cvt
__device__ __forceinline__ uint32_t packh2(float x, float y) {
    uint32_t r;
    asm("cvt.rn.f16x2.f32 %0, %2, %1;" : "=r"(r) : "f"(x), "f"(y));
    return r;
}

// ===========================================================================
// fused prep: blockIdx.z 0..3 -> weight transpose; z==4 -> x hi/lo split.
// ===========================================================================
__global__ void prep_all(const float* __restrict__ x,
                         const float* __restrict__ Wq, const float* __restrict__ Wk,
                         const float* __restrict__ Wv, const float* __restrict__ Wo,
                         __half* __restrict__ xc, __half* __restrict__ wc)
{
    __shared__ float t[32][33];
    const int z = blockIdx.z;
    const int tx = threadIdx.x, ty = threadIdx.y;

    if (z == 4) {
        const int tid = (blockIdx.y * 24 + blockIdx.x) * 256 + ty * 32 + tx;
        const int nthreads = 24 * 24 * 256;              // 147456
        for (int i = tid; i < MTOT * 192; i += nthreads) {
            const int row = i / 192, c = (i % 192) * 4;
            const float4 v = ((const float4*)x)[i];
            __half h[4], l[4];
            const float vv[4] = {v.x, v.y, v.z, v.w};
            #pragma unroll
            for (int j = 0; j < 4; j++) {
                h[j] = __float2half(vv[j]);
                l[j] = __float2half(vv[j] - __half2float(h[j]));
            }
            __half* o = xc + (size_t)row * KC2 + c;
            *(uint2*)(o)       = *(uint2*)h;
            *(uint2*)(o + EMB) = *(uint2*)l;
        }
        return;
    }

    const float* W = (z == 0) ? Wq : (z == 1) ? Wk : (z == 2) ? Wv : Wo;
    __half* out = wc + (size_t)z * EMB * KC2;
    const int stride = (z < 2) ? KC2 : EMB;

    const int xg = blockIdx.x * 32 + tx;
    const int y0 = blockIdx.y * 32;
    #pragma unroll
    for (int i = ty; i < 32; i += 8)
        t[i][tx] = W[(size_t)(y0 + i) * EMB + xg];
    __syncthreads();
    #pragma unroll
    for (int i = ty; i < 32; i += 8) {
        const int n = blockIdx.x * 32 + i;
        const int k = y0 + tx;
        const __half h = __float2half(t[tx][i]);
        __half* o = out + (size_t)n * stride + k;
        o[0] = h;
        if (z < 2) o[EMB] = h;
    }
}

// ===========================================================================
// shared GEMM core (128x128): k-chunk 64, SW128-xor swizzle, 3-stage.
// ===========================================================================
#define GSTAGE (256 * 128)                    // 32768 B per stage
#define GEMM_SMEM (3 * GSTAGE)                // 98304 B

__device__ __forceinline__ void gemm_core(
    const __half* __restrict__ A, const __half* __restrict__ B,
    int strideA, int strideB, int ktot, uint32_t sb,
    int tid, int wm, int wn, int midx, int lrow, int m0, int n0,
    float acc[4][4][4])
{
    auto load_chunk = [&](int c, int s) {
        const uint32_t base = sb + s * GSTAGE;
        #pragma unroll
        for (int t = 0; t < 8; t++) {
            const int idx = tid + t * 256;        // 0..2047
            const int row = idx >> 3, seg = idx & 7;
            const uint32_t dst = base + row * 128 + ((seg ^ (row & 7)) * 16);
            const __half* src = (row < 128)
                ? A + (size_t)(m0 + row) * strideA + c * 64 + seg * 8
                : B + (size_t)(n0 + row - 128) * strideB + c * 64 + seg * 8;
            cpa16(dst, src);
        }
    };

    auto compute = [&](int s) {
        const uint32_t base = sb + s * GSTAGE;
        #pragma unroll
        for (int kk8 = 0; kk8 < 8; kk8 += 2) {
            uint32_t af[4][4];
            const int sa = kk8 + (midx >> 1);
            #pragma unroll
            for (int mt = 0; mt < 4; mt++) {
                const int r = wm + mt * 16 + (midx & 1) * 8 + lrow;
                ldm4(af[mt], base + r * 128 + ((sa ^ (r & 7)) * 16));
            }
            const int sbg = kk8 + (midx & 1);
            #pragma unroll
            for (int np = 0; np < 2; np++) {
                uint32_t bf4[4];
                const int rb = wn + np * 16 + (midx >> 1) * 8 + lrow;
                ldm4(bf4, base + 16384 + rb * 128 + ((sbg ^ (rb & 7)) * 16));
                #pragma unroll
                for (int h2 = 0; h2 < 2; h2++) {
                    const int nt = np * 2 + h2;
                    #pragma unroll
                    for (int mt = 0; mt < 4; mt++)
                        mma_f16(acc[mt][nt], af[mt], bf4[h2 * 2], bf4[h2 * 2 + 1]);
                }
            }
        }
    };

    const int nch = ktot / 64;
    load_chunk(0, 0); CP_COMMIT();
    load_chunk(1, 1); CP_COMMIT();
    for (int c = 0; c < nch; c++) {
        CP_WAIT1();
        __syncthreads();
        if (c + 2 < nch) load_chunk(c + 2, (c + 2) % 3);
        CP_COMMIT();
        compute(c % 3);
    }
}

// ===========================================================================
// fused QKV projection: blockIdx.z = {0:Q, 1:K, 2:V}
// ===========================================================================
__global__ __launch_bounds__(256, 2) void gemm_qkv(
    const __half* __restrict__ A, const __half* __restrict__ wc,
    const float* __restrict__ bq, const float* __restrict__ bk,
    const float* __restrict__ bv,
    __half* __restrict__ qh, __half* __restrict__ kh, __half* __restrict__ vh)
{
    extern __shared__ __half gsm[];
    const uint32_t sbA = smem_u32(gsm);
    const int tid = threadIdx.x;
    const int wid = tid >> 5, lane = tid & 31;
    const int midx = lane >> 3, lrow = lane & 7;
    const int m0 = blockIdx.y * 128, n0 = blockIdx.x * 128;
    const int wm = (wid & 1) * 64, wn = (wid >> 1) * 32;
    const int z = blockIdx.z;

    const __half* B = wc + (size_t)z * EMB * KC2;
    const int kdep = (z < 2) ? KC2 : EMB;
    const float* bias = (z == 0) ? bq : (z == 1) ? bk : bv;
    __half* out0 = (z == 0) ? qh : (z == 1) ? kh : vh;
    const float scale = (z == 0) ? LOG2E : 1.0f;

    float acc[4][4][4];
    #pragma unroll
    for (int a = 0; a < 4; a++)
        #pragma unroll
        for (int b = 0; b < 4; b++)
            #pragma unroll
            for (int c = 0; c < 4; c++) acc[a][b][c] = 0.f;

    gemm_core(A, B, KC2, kdep, kdep, sbA, tid, wm, wn, midx, lrow, m0, n0, acc);

    #pragma unroll
    for (int mt = 0; mt < 4; mt++) {
        #pragma unroll
        for (int nt = 0; nt < 4; nt++) {
            const int r  = wm + mt * 16 + (lane >> 2);
            const int cc = n0 + wn + nt * 8 + (lane & 3) * 2;
            #pragma unroll
            for (int half = 0; half < 2; half++) {       // rows r, r+8
                const int m = m0 + r + half * 8;
                const float v0 = (acc[mt][nt][half * 2]     + bias[cc])     * scale;
                const float v1 = (acc[mt][nt][half * 2 + 1] + bias[cc + 1]) * scale;
                const int bb = m >> 11, nn = m & (SEQ - 1);
                const int h = cc / HD, d = cc % HD;       // pair stays in one head
                const size_t i0 = ((size_t)(bb * HEADS + h) * SEQ + nn) * HD + d;
                *(uint32_t*)(out0 + i0) = packh2(v0, v1);
            }
        }
    }
}

// ===========================================================================
// output projection, 64x128 tile (wave-quantization fix): K-depth 768,
// single product, fp32 natural [m][768]. 8 warps = 2m x 4n, warp 32x32.
// Stage: 64 A-rows + 128 B-rows = 192 rows x 128B.
// ===========================================================================
#define GO_STAGE (192 * 128)                  // 24576 B per stage
#define GO_SMEM  (3 * GO_STAGE)               // 73728 B

__global__ __launch_bounds__(256, 2) void gemm_o64(
    const __half* __restrict__ A, const __half* __restrict__ B,
    const float* __restrict__ bias, float* __restrict__ outf)
{
    extern __shared__ __half gsm[];
    const uint32_t sb = smem_u32(gsm);
    const int tid = threadIdx.x;
    const int wid = tid >> 5, lane = tid & 31;
    const int midx = lane >> 3, lrow = lane & 7;
    const int m0 = blockIdx.y * 64, n0 = blockIdx.x * 128;
    const int wm = (wid & 1) * 32, wn = (wid >> 1) * 32;

    float acc[2][4][4];
    #pragma unroll
    for (int a = 0; a < 2; a++)
        #pragma unroll
        for (int b = 0; b < 4; b++)
            #pragma unroll
            for (int c = 0; c < 4; c++) acc[a][b][c] = 0.f;

    auto load_chunk = [&](int c, int s) {
        const uint32_t base = sb + s * GO_STAGE;
        #pragma unroll
        for (int t = 0; t < 6; t++) {
            const int idx = tid + t * 256;        // 0..1535
            const int row = idx >> 3, seg = idx & 7;
            const uint32_t dst = base + row * 128 + ((seg ^ (row & 7)) * 16);
            const __half* src = (row < 64)
                ? A + (size_t)(m0 + row) * EMB + c * 64 + seg * 8
                : B + (size_t)(n0 + row - 64) * EMB + c * 64 + seg * 8;
            cpa16(dst, src);
        }
    };

    auto compute = [&](int s) {
        const uint32_t base = sb + s * GO_STAGE;
        #pragma unroll
        for (int kk8 = 0; kk8 < 8; kk8 += 2) {
            uint32_t af[2][4];
            const int sa = kk8 + (midx >> 1);
            #pragma unroll
            for (int mt = 0; mt < 2; mt++) {
                const int r = wm + mt * 16 + (midx & 1) * 8 + lrow;
                ldm4(af[mt], base + r * 128 + ((sa ^ (r & 7)) * 16));
            }
            const int sbg = kk8 + (midx & 1);
            #pragma unroll
            for (int np = 0; np < 2; np++) {
                uint32_t bf4[4];
                const int rb = wn + np * 16 + (midx >> 1) * 8 + lrow;
                ldm4(bf4, base + 8192 + rb * 128 + ((sbg ^ (rb & 7)) * 16));
                #pragma unroll
                for (int h2 = 0; h2 < 2; h2++) {
                    const int nt = np * 2 + h2;
                    #pragma unroll
                    for (int mt = 0; mt < 2; mt++)
                        mma_f16(acc[mt][nt], af[mt], bf4[h2 * 2], bf4[h2 * 2 + 1]);
                }
            }
        }
    };

    const int nch = EMB / 64;   // 12
    load_chunk(0, 0); CP_COMMIT();
    load_chunk(1, 1); CP_COMMIT();
    for (int c = 0; c < nch; c++) {
        CP_WAIT1();
        __syncthreads();
        if (c + 2 < nch) load_chunk(c + 2, (c + 2) % 3);
        CP_COMMIT();
        compute(c % 3);
    }

    #pragma unroll
    for (int mt = 0; mt < 2; mt++) {
        #pragma unroll
        for (int nt = 0; nt < 4; nt++) {
            const int r  = wm + mt * 16 + (lane >> 2);
            const int cc = n0 + wn + nt * 8 + (lane & 3) * 2;
            #pragma unroll
            for (int half = 0; half < 2; half++) {
                const int m = m0 + r + half * 8;
                *(float2*)(outf + (size_t)m * EMB + cc) = make_float2(
                    acc[mt][nt][half * 2] + bias[cc],
                    acc[mt][nt][half * 2 + 1] + bias[cc + 1]);
            }
        }
    }
}

// ===========================================================================
// Flash attention (R10 schedule — best known): S = qh·kh, PV single-product,
// MUFU exp2, split-phase K/V prefetch, conditional oacc rescale.
// ===========================================================================
#define APAD 104
#define ATTN_SMEM ((128 + 2 * 64) * APAD * 2)            // 53248 B

__global__ __launch_bounds__(256, 2) void attn_mma()
{
    extern __shared__ __half asmem[];
    const uint32_t sQh = smem_u32(asmem);
    const uint32_t sKh = sQh + 128 * APAD * 2;
    const uint32_t sVh = sKh + 64 * APAD * 2;

    const int tid = threadIdx.x;
    const int wid = tid >> 5, lane = tid & 31;
    const int midx = lane >> 3, lrow = lane & 7;
    const int q0 = blockIdx.x * 128;
    const int bh = blockIdx.y;

    const __half* bQh = g_Qh + (size_t)bh * SEQ * HD;
    const __half* bKh = g_Kh + (size_t)bh * SEQ * HD;
    const __half* bVh = g_Vh + (size_t)bh * SEQ * HD;

    auto loadK = [&](int kt) {
        #pragma unroll
        for (int t = 0; t < 3; t++) {
            const int i = tid + t * 256;                 // < 768
            const int r = i / 12, seg = i % 12;
            cpa16(sKh + (r * APAD + seg * 8) * 2, bKh + (size_t)(kt * 64 + r) * HD + seg * 8);
        }
    };
    auto loadV = [&](int kt) {
        #pragma unroll
        for (int t = 0; t < 3; t++) {
            const int i = tid + t * 256;                 // < 768
            const int r = i / 12, seg = i % 12;
            cpa16(sVh + (r * APAD + seg * 8) * 2, bVh + (size_t)(kt * 64 + r) * HD + seg * 8);
        }
    };

    // prologue: Q + K0 in group 0, V0 in group 1
    #pragma unroll
    for (int t = 0; t < 6; t++) {
        const int i = tid + t * 256;                     // < 1536
        const int r = i / 12, seg = i % 12;
        cpa16(sQh + (r * APAD + seg * 8) * 2, bQh + (size_t)(q0 + r) * HD + seg * 8);
    }
    loadK(0);
    CP_COMMIT();
    loadV(0);
    CP_COMMIT();

    float m0v = -INFINITY, m1v = -INFINITY, l0 = 0.f, l1 = 0.f;
    float oacc[12][4];
    #pragma unroll
    for (int d = 0; d < 12; d++)
        #pragma unroll
        for (int c = 0; c < 4; c++) oacc[d][c] = 0.f;

    const int NT = SEQ / 64;
    for (int kt = 0; kt < NT; kt++) {
        CP_WAIT1();                      // K(kt) (+Q on first iter) ready
        __syncthreads();

        // ---- S (log2-space) = Qh Kh^T, single product ----
        float sacc[8][4];
        #pragma unroll
        for (int n = 0; n < 8; n++)
            #pragma unroll
            for (int c = 0; c < 4; c++) sacc[n][c] = 0.f;

        #pragma unroll
        for (int kd = 0; kd < HD; kd += 16) {
            uint32_t qh4[4];
            const uint32_t qoff =
                ((wid * 16 + (midx & 1) * 8 + lrow) * APAD + kd + (midx >> 1) * 8) * 2;
            ldm4(qh4, sQh + qoff);
            #pragma unroll
            for (int np = 0; np < 4; np++) {
                uint32_t kh4[4];
                const uint32_t koff =
                    ((np * 16 + (midx >> 1) * 8 + lrow) * APAD + kd + (midx & 1) * 8) * 2;
                ldm4(kh4, sKh + koff);
                #pragma unroll
                for (int h2 = 0; h2 < 2; h2++)
                    mma_f16(sacc[np * 2 + h2], qh4, kh4[h2 * 2], kh4[h2 * 2 + 1]);
            }
        }

        __syncthreads();                 // all warps done reading K buffer
        if (kt + 1 < NT) loadK(kt + 1);  // overlaps softmax + PV below
        CP_COMMIT();

        // ---- online softmax in log2 space (MUFU ex2; 4-lane row groups) ----
        float mx0 = -INFINITY, mx1 = -INFINITY;
        #pragma unroll
        for (int n = 0; n < 8; n++) {
            mx0 = fmaxf(mx0, fmaxf(sacc[n][0], sacc[n][1]));
            mx1 = fmaxf(mx1, fmaxf(sacc[n][2], sacc[n][3]));
        }
        mx0 = fmaxf(mx0, __shfl_xor_sync(0xffffffffu, mx0, 1));
        mx0 = fmaxf(mx0, __shfl_xor_sync(0xffffffffu, mx0, 2));
        mx1 = fmaxf(mx1, __shfl_xor_sync(0xffffffffu, mx1, 1));
        mx1 = fmaxf(mx1, __shfl_xor_sync(0xffffffffu, mx1, 2));

        const float mn0 = fmaxf(m0v, mx0), a0v = ex2f(m0v - mn0);
        const float mn1 = fmaxf(m1v, mx1), a1v = ex2f(m1v - mn1);
        m0v = mn0; m1v = mn1;

        float rs0 = 0.f, rs1 = 0.f;
        #pragma unroll
        for (int n = 0; n < 8; n++) {
            sacc[n][0] = ex2f(sacc[n][0] - mn0); rs0 += sacc[n][0];
            sacc[n][1] = ex2f(sacc[n][1] - mn0); rs0 += sacc[n][1];
            sacc[n][2] = ex2f(sacc[n][2] - mn1); rs1 += sacc[n][2];
            sacc[n][3] = ex2f(sacc[n][3] - mn1); rs1 += sacc[n][3];
        }
        rs0 += __shfl_xor_sync(0xffffffffu, rs0, 1);
        rs0 += __shfl_xor_sync(0xffffffffu, rs0, 2);
        rs1 += __shfl_xor_sync(0xffffffffu, rs1, 1);
        rs1 += __shfl_xor_sync(0xffffffffu, rs1, 2);
        l0 = l0 * a0v + rs0;
        l1 = l1 * a1v + rs1;

        // rescale only when the running max actually moved (alpha < 1)
        if (a0v != 1.f || a1v != 1.f) {
            #pragma unroll
            for (int d = 0; d < 12; d++) {
                oacc[d][0] *= a0v; oacc[d][1] *= a0v;
                oacc[d][2] *= a1v; oacc[d][3] *= a1v;
            }
        }

        CP_WAIT1();                      // V(kt) ready (K(kt+1) still in flight)
        __syncthreads();

        // ---- O += P V  (single fp16 product; P packed via one cvt) ----
        #pragma unroll
        for (int st = 0; st < 4; st++) {
            uint32_t ph[4];
            ph[0] = packh2(sacc[2*st][0],   sacc[2*st][1]);
            ph[1] = packh2(sacc[2*st][2],   sacc[2*st][3]);
            ph[2] = packh2(sacc[2*st+1][0], sacc[2*st+1][1]);
            ph[3] = packh2(sacc[2*st+1][2], sacc[2*st+1][3]);
            #pragma unroll
            for (int dp = 0; dp < 6; dp++) {
                uint32_t vh4[4];
                const uint32_t voff =
                    ((st * 16 + (midx & 1) * 8 + lrow) * APAD + dp * 16 + (midx >> 1) * 8) * 2;
                ldm4t(vh4, sVh + voff);
                mma_f16(oacc[dp*2],   ph, vh4[0], vh4[1]);
                mma_f16(oacc[dp*2+1], ph, vh4[2], vh4[3]);
            }
        }

        __syncthreads();                 // all warps done reading V buffer
        if (kt + 1 < NT) loadV(kt + 1);  // overlaps next S-phase
        CP_COMMIT();
    }

    // epilogue: /(l*sqrt(96)), hi-only fp16 into O-projection operand
    const float inv0 = 0.10206207261596577f / l0;
    const float inv1 = 0.10206207261596577f / l1;
    const int bb = bh >> 3, h = bh & 7;
    const int row0 = q0 + wid * 16 + (lane >> 2);
    __half* o0 = g_Oc + (size_t)(bb * SEQ + row0) * EMB + h * HD + (lane & 3) * 2;
    __half* o1 = o0 + (size_t)8 * EMB;
    #pragma unroll
    for (int dp = 0; dp < 12; dp++) {
        *(uint32_t*)(o0 + dp * 8) = packh2(oacc[dp][0] * inv0, oacc[dp][1] * inv0);
        *(uint32_t*)(o1 + dp * 8) = packh2(oacc[dp][2] * inv1, oacc[dp][3] * inv1);
    }
}

// ---------------------------------------------------------------------------
extern "C" void kernel_launch(void* const* d_in, const int* in_sizes, int n_in,
                              void* d_out, int out_size)
{
    const float* x  = (const float*)d_in[0];
    const float* Wq = (const float*)d_in[1];
    const float* bq = (const float*)d_in[2];
    const float* Wk = (const float*)d_in[3];
    const float* bk = (const float*)d_in[4];
    const float* Wv = (const float*)d_in[5];
    const float* bv = (const float*)d_in[6];
    const float* Wo = (const float*)d_in[7];
    const float* bo = (const float*)d_in[8];
    float* out = (float*)d_out;

    __half *xc, *oc, *wc, *qh, *kh, *vh;
    cudaGetSymbolAddress((void**)&xc, g_Xc);
    cudaGetSymbolAddress((void**)&oc, g_Oc);
    cudaGetSymbolAddress((void**)&wc, g_Wc);
    cudaGetSymbolAddress((void**)&qh, g_Qh);
    cudaGetSymbolAddress((void**)&kh, g_Kh);
    cudaGetSymbolAddress((void**)&vh, g_Vh);

    prep_all<<<dim3(EMB / 32, EMB / 32, 5), dim3(32, 8)>>>(x, Wq, Wk, Wv, Wo, xc, wc);

    cudaFuncSetAttribute(gemm_qkv, cudaFuncAttributeMaxDynamicSharedMemorySize, GEMM_SMEM);
    cudaFuncSetAttribute(gemm_o64, cudaFuncAttributeMaxDynamicSharedMemorySize, GO_SMEM);

    gemm_qkv<<<dim3(EMB / 128, MTOT / 128, 3), 256, GEMM_SMEM>>>(
        xc, wc, bq, bk, bv, qh, kh, vh);

    cudaFuncSetAttribute(attn_mma, cudaFuncAttributeMaxDynamicSharedMemorySize, ATTN_SMEM);
    attn_mma<<<dim3(SEQ / 128, BHN), 256, ATTN_SMEM>>>();

    __half* wco = wc + (size_t)3 * EMB * KC2;
    gemm_o64<<<dim3(EMB / 128, MTOT / 64), 256, GO_SMEM>>>(oc, wco, bo, out);
}

// round 15
// speedup vs baseline: 1.0084x; 1.0084x over previous
#include <cuda_runtime.h>
#include <cuda_fp16.h>
#include <cstdint>
#include <math.h>

#define EMB   768
#define HEADS 8
#define HD    96
#define BATCH 4
#define SEQ   2048
#define BHN   (BATCH*HEADS)
#define MTOT  (BATCH*SEQ)
#define KC2   (2*EMB)        // 1536 (compensated operands: Q, K)
#define LOG2E 1.4426950408889634f

// ---------------- scratch globals (module-load allocated) -------------------
__device__ __half g_Xc[(size_t)MTOT * KC2];    // x split [ah, al]
__device__ __half g_Oc[(size_t)MTOT * EMB];    // attn-out hi-only fp16
__device__ __half g_Wc[4][(size_t)EMB * KC2];  // W^T: Q/K=[bh,bh] str 1536, V/O=[bh] str 768
__device__ __half g_Qh[(size_t)BHN * SEQ * HD];
__device__ __half g_Kh[(size_t)BHN * SEQ * HD];
__device__ __half g_Vh[(size_t)BHN * SEQ * HD];

// ---------------- helpers ---------------------------------------------------
__device__ __forceinline__ uint32_t smem_u32(const void* p) {
    uint32_t a;
    asm("{ .reg .u64 t; cvta.to.shared.u64 t, %1; cvt.u32.u64 %0, t; }" : "=r"(a) : "l"(p));
    return a;
}
__device__ __forceinline__ void cpa16(uint32_t d, const void* s) {
    asm volatile("cp.async.cg.shared.global [%0], [%1], 16;" :: "r"(d), "l"(s));
}
#define CP_COMMIT() asm volatile("cp.async.commit_group;")
#define CP_WAIT0()  asm volatile("cp.async.wait_group 0;")
#define CP_WAIT1()  asm volatile("cp.async.wait_group 1;")

__device__ __forceinline__ void ldm4(uint32_t* r, uint32_t addr) {
    asm volatile("ldmatrix.sync.aligned.m8n8.x4.shared.b16 {%0,%1,%2,%3}, [%4];"
        : "=r"(r[0]), "=r"(r[1]), "=r"(r[2]), "=r"(r[3]) : "r"(addr));
}
__device__ __forceinline__ void ldm4t(uint32_t* r, uint32_t addr) {
    asm volatile("ldmatrix.sync.aligned.m8n8.x4.trans.shared.b16 {%0,%1,%2,%3}, [%4];"
        : "=r"(r[0]), "=r"(r[1]), "=r"(r[2]), "=r"(r[3]) : "r"(addr));
}
__device__ __forceinline__ void mma_f16(float* c, const uint32_t* a, uint32_t b0, uint32_t b1) {
    asm volatile("mma.sync.aligned.m16n8k16.row.col.f32.f16.f16.f32 "
        "{%0,%1,%2,%3}, {%4,%5,%6,%7}, {%8,%9}, {%0,%1,%2,%3};"
        : "+f"(c[0]), "+f"(c[1]), "+f"(c[2]), "+f"(c[3])
        : "r"(a[0]), "r"(a[1]), "r"(a[2]), "r"(a[3]), "r"(b0), "r"(b1));
}
// guaranteed-MUFU exp2
__device__ __forceinline__ float ex2f(float x) {
    float y;
    asm("ex2.approx.ftz.f32 %0, %1;" : "=f"(y) : "f"(x));
    return y;
}
// pack two fp32 -> fp16x2 {lo=x, hi=y} in one cvt
__device__ __forceinline__ uint32_t packh2(float x, float y) {
    uint32_t r;
    asm("cvt.rn.f16x2.f32 %0, %2, %1;" : "=r"(r) : "f"(x), "f"(y));
    return r;
}

// ===========================================================================
// fused prep: blockIdx.z 0..3 -> weight transpose; z==4 -> x hi/lo split.
// ===========================================================================
__global__ void prep_all(const float* __restrict__ x,
                         const float* __restrict__ Wq, const float* __restrict__ Wk,
                         const float* __restrict__ Wv, const float* __restrict__ Wo,
                         __half* __restrict__ xc, __half* __restrict__ wc)
{
    __shared__ float t[32][33];
    const int z = blockIdx.z;
    const int tx = threadIdx.x, ty = threadIdx.y;

    if (z == 4) {
        const int tid = (blockIdx.y * 24 + blockIdx.x) * 256 + ty * 32 + tx;
        const int nthreads = 24 * 24 * 256;              // 147456
        for (int i = tid; i < MTOT * 192; i += nthreads) {
            const int row = i / 192, c = (i % 192) * 4;
            const float4 v = ((const float4*)x)[i];
            __half h[4], l[4];
            const float vv[4] = {v.x, v.y, v.z, v.w};
            #pragma unroll
            for (int j = 0; j < 4; j++) {
                h[j] = __float2half(vv[j]);
                l[j] = __float2half(vv[j] - __half2float(h[j]));
            }
            __half* o = xc + (size_t)row * KC2 + c;
            *(uint2*)(o)       = *(uint2*)h;
            *(uint2*)(o + EMB) = *(uint2*)l;
        }
        return;
    }

    const float* W = (z == 0) ? Wq : (z == 1) ? Wk : (z == 2) ? Wv : Wo;
    __half* out = wc + (size_t)z * EMB * KC2;
    const int stride = (z < 2) ? KC2 : EMB;

    const int xg = blockIdx.x * 32 + tx;
    const int y0 = blockIdx.y * 32;
    #pragma unroll
    for (int i = ty; i < 32; i += 8)
        t[i][tx] = W[(size_t)(y0 + i) * EMB + xg];
    __syncthreads();
    #pragma unroll
    for (int i = ty; i < 32; i += 8) {
        const int n = blockIdx.x * 32 + i;
        const int k = y0 + tx;
        const __half h = __float2half(t[tx][i]);
        __half* o = out + (size_t)n * stride + k;
        o[0] = h;
        if (z < 2) o[EMB] = h;
    }
}

// ===========================================================================
// shared GEMM core (128x128): k-chunk 64, SW128-xor swizzle, 3-stage.
// ===========================================================================
#define GSTAGE (256 * 128)                    // 32768 B per stage
#define GEMM_SMEM (3 * GSTAGE)                // 98304 B

__device__ __forceinline__ void gemm_core(
    const __half* __restrict__ A, const __half* __restrict__ B,
    int strideA, int strideB, int ktot, uint32_t sb,
    int tid, int wm, int wn, int midx, int lrow, int m0, int n0,
    float acc[4][4][4])
{
    auto load_chunk = [&](int c, int s) {
        const uint32_t base = sb + s * GSTAGE;
        #pragma unroll
        for (int t = 0; t < 8; t++) {
            const int idx = tid + t * 256;        // 0..2047
            const int row = idx >> 3, seg = idx & 7;
            const uint32_t dst = base + row * 128 + ((seg ^ (row & 7)) * 16);
            const __half* src = (row < 128)
                ? A + (size_t)(m0 + row) * strideA + c * 64 + seg * 8
                : B + (size_t)(n0 + row - 128) * strideB + c * 64 + seg * 8;
            cpa16(dst, src);
        }
    };

    auto compute = [&](int s) {
        const uint32_t base = sb + s * GSTAGE;
        #pragma unroll
        for (int kk8 = 0; kk8 < 8; kk8 += 2) {
            uint32_t af[4][4];
            const int sa = kk8 + (midx >> 1);
            #pragma unroll
            for (int mt = 0; mt < 4; mt++) {
                const int r = wm + mt * 16 + (midx & 1) * 8 + lrow;
                ldm4(af[mt], base + r * 128 + ((sa ^ (r & 7)) * 16));
            }
            const int sbg = kk8 + (midx & 1);
            #pragma unroll
            for (int np = 0; np < 2; np++) {
                uint32_t bf4[4];
                const int rb = wn + np * 16 + (midx >> 1) * 8 + lrow;
                ldm4(bf4, base + 16384 + rb * 128 + ((sbg ^ (rb & 7)) * 16));
                #pragma unroll
                for (int h2 = 0; h2 < 2; h2++) {
                    const int nt = np * 2 + h2;
                    #pragma unroll
                    for (int mt = 0; mt < 4; mt++)
                        mma_f16(acc[mt][nt], af[mt], bf4[h2 * 2], bf4[h2 * 2 + 1]);
                }
            }
        }
    };

    const int nch = ktot / 64;
    load_chunk(0, 0); CP_COMMIT();
    load_chunk(1, 1); CP_COMMIT();
    for (int c = 0; c < nch; c++) {
        CP_WAIT1();
        __syncthreads();
        if (c + 2 < nch) load_chunk(c + 2, (c + 2) % 3);
        CP_COMMIT();
        compute(c % 3);
    }
}

// ===========================================================================
// fused QKV projection: blockIdx.z = {0:Q, 1:K, 2:V}
// ===========================================================================
__global__ __launch_bounds__(256, 2) void gemm_qkv(
    const __half* __restrict__ A, const __half* __restrict__ wc,
    const float* __restrict__ bq, const float* __restrict__ bk,
    const float* __restrict__ bv,
    __half* __restrict__ qh, __half* __restrict__ kh, __half* __restrict__ vh)
{
    extern __shared__ __half gsm[];
    const uint32_t sbA = smem_u32(gsm);
    const int tid = threadIdx.x;
    const int wid = tid >> 5, lane = tid & 31;
    const int midx = lane >> 3, lrow = lane & 7;
    const int m0 = blockIdx.y * 128, n0 = blockIdx.x * 128;
    const int wm = (wid & 1) * 64, wn = (wid >> 1) * 32;
    const int z = blockIdx.z;

    const __half* B = wc + (size_t)z * EMB * KC2;
    const int kdep = (z < 2) ? KC2 : EMB;
    const float* bias = (z == 0) ? bq : (z == 1) ? bk : bv;
    __half* out0 = (z == 0) ? qh : (z == 1) ? kh : vh;
    const float scale = (z == 0) ? LOG2E : 1.0f;

    float acc[4][4][4];
    #pragma unroll
    for (int a = 0; a < 4; a++)
        #pragma unroll
        for (int b = 0; b < 4; b++)
            #pragma unroll
            for (int c = 0; c < 4; c++) acc[a][b][c] = 0.f;

    gemm_core(A, B, KC2, kdep, kdep, sbA, tid, wm, wn, midx, lrow, m0, n0, acc);

    #pragma unroll
    for (int mt = 0; mt < 4; mt++) {
        #pragma unroll
        for (int nt = 0; nt < 4; nt++) {
            const int r  = wm + mt * 16 + (lane >> 2);
            const int cc = n0 + wn + nt * 8 + (lane & 3) * 2;
            #pragma unroll
            for (int half = 0; half < 2; half++) {       // rows r, r+8
                const int m = m0 + r + half * 8;
                const float v0 = (acc[mt][nt][half * 2]     + bias[cc])     * scale;
                const float v1 = (acc[mt][nt][half * 2 + 1] + bias[cc + 1]) * scale;
                const int bb = m >> 11, nn = m & (SEQ - 1);
                const int h = cc / HD, d = cc % HD;       // pair stays in one head
                const size_t i0 = ((size_t)(bb * HEADS + h) * SEQ + nn) * HD + d;
                *(uint32_t*)(out0 + i0) = packh2(v0, v1);
            }
        }
    }
}

// ===========================================================================
// output projection (R13 optimum: 128x128 tile): K-depth 768 single product,
// fp32 natural [m][768]
// ===========================================================================
__global__ __launch_bounds__(256, 2) void gemm_o(
    const __half* __restrict__ A, const __half* __restrict__ B,
    const float* __restrict__ bias, float* __restrict__ outf)
{
    extern __shared__ __half gsm[];
    const uint32_t sbA = smem_u32(gsm);
    const int tid = threadIdx.x;
    const int wid = tid >> 5, lane = tid & 31;
    const int midx = lane >> 3, lrow = lane & 7;
    const int m0 = blockIdx.y * 128, n0 = blockIdx.x * 128;
    const int wm = (wid & 1) * 64, wn = (wid >> 1) * 32;

    float acc[4][4][4];
    #pragma unroll
    for (int a = 0; a < 4; a++)
        #pragma unroll
        for (int b = 0; b < 4; b++)
            #pragma unroll
            for (int c = 0; c < 4; c++) acc[a][b][c] = 0.f;

    gemm_core(A, B, EMB, EMB, EMB, sbA, tid, wm, wn, midx, lrow, m0, n0, acc);

    #pragma unroll
    for (int mt = 0; mt < 4; mt++) {
        #pragma unroll
        for (int nt = 0; nt < 4; nt++) {
            const int r  = wm + mt * 16 + (lane >> 2);
            const int cc = n0 + wn + nt * 8 + (lane & 3) * 2;
            #pragma unroll
            for (int half = 0; half < 2; half++) {
                const int m = m0 + r + half * 8;
                *(float2*)(outf + (size_t)m * EMB + cc) = make_float2(
                    acc[mt][nt][half * 2] + bias[cc],
                    acc[mt][nt][half * 2 + 1] + bias[cc + 1]);
            }
        }
    }
}

// ===========================================================================
// Flash attention (R10 schedule): S = qh·kh, PV single-product, MUFU exp2,
// split-phase K/V prefetch, conditional oacc rescale, lane-partial l
// (denominator reduced once at epilogue — alpha is uniform per row group).
// ===========================================================================
#define APAD 104
#define ATTN_SMEM ((128 + 2 * 64) * APAD * 2)            // 53248 B

__global__ __launch_bounds__(256, 2) void attn_mma()
{
    extern __shared__ __half asmem[];
    const uint32_t sQh = smem_u32(asmem);
    const uint32_t sKh = sQh + 128 * APAD * 2;
    const uint32_t sVh = sKh + 64 * APAD * 2;

    const int tid = threadIdx.x;
    const int wid = tid >> 5, lane = tid & 31;
    const int midx = lane >> 3, lrow = lane & 7;
    const int q0 = blockIdx.x * 128;
    const int bh = blockIdx.y;

    const __half* bQh = g_Qh + (size_t)bh * SEQ * HD;
    const __half* bKh = g_Kh + (size_t)bh * SEQ * HD;
    const __half* bVh = g_Vh + (size_t)bh * SEQ * HD;

    auto loadK = [&](int kt) {
        #pragma unroll
        for (int t = 0; t < 3; t++) {
            const int i = tid + t * 256;                 // < 768
            const int r = i / 12, seg = i % 12;
            cpa16(sKh + (r * APAD + seg * 8) * 2, bKh + (size_t)(kt * 64 + r) * HD + seg * 8);
        }
    };
    auto loadV = [&](int kt) {
        #pragma unroll
        for (int t = 0; t < 3; t++) {
            const int i = tid + t * 256;                 // < 768
            const int r = i / 12, seg = i % 12;
            cpa16(sVh + (r * APAD + seg * 8) * 2, bVh + (size_t)(kt * 64 + r) * HD + seg * 8);
        }
    };

    // prologue: Q + K0 in group 0, V0 in group 1
    #pragma unroll
    for (int t = 0; t < 6; t++) {
        const int i = tid + t * 256;                     // < 1536
        const int r = i / 12, seg = i % 12;
        cpa16(sQh + (r * APAD + seg * 8) * 2, bQh + (size_t)(q0 + r) * HD + seg * 8);
    }
    loadK(0);
    CP_COMMIT();
    loadV(0);
    CP_COMMIT();

    float m0v = -INFINITY, m1v = -INFINITY, l0 = 0.f, l1 = 0.f;  // l: lane-partial
    float oacc[12][4];
    #pragma unroll
    for (int d = 0; d < 12; d++)
        #pragma unroll
        for (int c = 0; c < 4; c++) oacc[d][c] = 0.f;

    const int NT = SEQ / 64;
    for (int kt = 0; kt < NT; kt++) {
        CP_WAIT1();                      // K(kt) (+Q on first iter) ready
        __syncthreads();

        // ---- S (log2-space) = Qh Kh^T, single product ----
        float sacc[8][4];
        #pragma unroll
        for (int n = 0; n < 8; n++)
            #pragma unroll
            for (int c = 0; c < 4; c++) sacc[n][c] = 0.f;

        #pragma unroll
        for (int kd = 0; kd < HD; kd += 16) {
            uint32_t qh4[4];
            const uint32_t qoff =
                ((wid * 16 + (midx & 1) * 8 + lrow) * APAD + kd + (midx >> 1) * 8) * 2;
            ldm4(qh4, sQh + qoff);
            #pragma unroll
            for (int np = 0; np < 4; np++) {
                uint32_t kh4[4];
                const uint32_t koff =
                    ((np * 16 + (midx >> 1) * 8 + lrow) * APAD + kd + (midx & 1) * 8) * 2;
                ldm4(kh4, sKh + koff);
                #pragma unroll
                for (int h2 = 0; h2 < 2; h2++)
                    mma_f16(sacc[np * 2 + h2], qh4, kh4[h2 * 2], kh4[h2 * 2 + 1]);
            }
        }

        __syncthreads();                 // all warps done reading K buffer
        if (kt + 1 < NT) loadK(kt + 1);  // overlaps softmax + PV below
        CP_COMMIT();

        // ---- online softmax in log2 space (MUFU ex2; 4-lane row groups) ----
        float mx0 = -INFINITY, mx1 = -INFINITY;
        #pragma unroll
        for (int n = 0; n < 8; n++) {
            mx0 = fmaxf(mx0, fmaxf(sacc[n][0], sacc[n][1]));
            mx1 = fmaxf(mx1, fmaxf(sacc[n][2], sacc[n][3]));
        }
        mx0 = fmaxf(mx0, __shfl_xor_sync(0xffffffffu, mx0, 1));
        mx0 = fmaxf(mx0, __shfl_xor_sync(0xffffffffu, mx0, 2));
        mx1 = fmaxf(mx1, __shfl_xor_sync(0xffffffffu, mx1, 1));
        mx1 = fmaxf(mx1, __shfl_xor_sync(0xffffffffu, mx1, 2));

        const float mn0 = fmaxf(m0v, mx0), a0v = ex2f(m0v - mn0);
        const float mn1 = fmaxf(m1v, mx1), a1v = ex2f(m1v - mn1);
        m0v = mn0; m1v = mn1;

        float rs0 = 0.f, rs1 = 0.f;      // this lane's 16-value partial sums
        #pragma unroll
        for (int n = 0; n < 8; n++) {
            sacc[n][0] = ex2f(sacc[n][0] - mn0); rs0 += sacc[n][0];
            sacc[n][1] = ex2f(sacc[n][1] - mn0); rs0 += sacc[n][1];
            sacc[n][2] = ex2f(sacc[n][2] - mn1); rs1 += sacc[n][2];
            sacc[n][3] = ex2f(sacc[n][3] - mn1); rs1 += sacc[n][3];
        }
        // lane-partial update: alpha is uniform across the 4-lane row group,
        // so deferring the cross-lane sum to the epilogue is exact.
        l0 = l0 * a0v + rs0;
        l1 = l1 * a1v + rs1;

        // rescale only when the running max actually moved (alpha < 1)
        if (a0v != 1.f || a1v != 1.f) {
            #pragma unroll
            for (int d = 0; d < 12; d++) {
                oacc[d][0] *= a0v; oacc[d][1] *= a0v;
                oacc[d][2] *= a1v; oacc[d][3] *= a1v;
            }
        }

        CP_WAIT1();                      // V(kt) ready (K(kt+1) still in flight)
        __syncthreads();

        // ---- O += P V  (single fp16 product; P packed via one cvt) ----
        #pragma unroll
        for (int st = 0; st < 4; st++) {
            uint32_t ph[4];
            ph[0] = packh2(sacc[2*st][0],   sacc[2*st][1]);
            ph[1] = packh2(sacc[2*st][2],   sacc[2*st][3]);
            ph[2] = packh2(sacc[2*st+1][0], sacc[2*st+1][1]);
            ph[3] = packh2(sacc[2*st+1][2], sacc[2*st+1][3]);
            #pragma unroll
            for (int dp = 0; dp < 6; dp++) {
                uint32_t vh4[4];
                const uint32_t voff =
                    ((st * 16 + (midx & 1) * 8 + lrow) * APAD + dp * 16 + (midx >> 1) * 8) * 2;
                ldm4t(vh4, sVh + voff);
                mma_f16(oacc[dp*2],   ph, vh4[0], vh4[1]);
                mma_f16(oacc[dp*2+1], ph, vh4[2], vh4[3]);
            }
        }

        __syncthreads();                 // all warps done reading V buffer
        if (kt + 1 < NT) loadV(kt + 1);  // overlaps next S-phase
        CP_COMMIT();
    }

    // finalize lane-partial denominators (one cross-lane reduction total)
    l0 += __shfl_xor_sync(0xffffffffu, l0, 1);
    l0 += __shfl_xor_sync(0xffffffffu, l0, 2);
    l1 += __shfl_xor_sync(0xffffffffu, l1, 1);
    l1 += __shfl_xor_sync(0xffffffffu, l1, 2);

    // epilogue: /(l*sqrt(96)), hi-only fp16 into O-projection operand
    const float inv0 = 0.10206207261596577f / l0;
    const float inv1 = 0.10206207261596577f / l1;
    const int bb = bh >> 3, h = bh & 7;
    const int row0 = q0 + wid * 16 + (lane >> 2);
    __half* o0 = g_Oc + (size_t)(bb * SEQ + row0) * EMB + h * HD + (lane & 3) * 2;
    __half* o1 = o0 + (size_t)8 * EMB;
    #pragma unroll
    for (int dp = 0; dp < 12; dp++) {
        *(uint32_t*)(o0 + dp * 8) = packh2(oacc[dp][0] * inv0, oacc[dp][1] * inv0);
        *(uint32_t*)(o1 + dp * 8) = packh2(oacc[dp][2] * inv1, oacc[dp][3] * inv1);
    }
}

// ---------------------------------------------------------------------------
extern "C" void kernel_launch(void* const* d_in, const int* in_sizes, int n_in,
                              void* d_out, int out_size)
{
    const float* x  = (const float*)d_in[0];
    const float* Wq = (const float*)d_in[1];
    const float* bq = (const float*)d_in[2];
    const float* Wk = (const float*)d_in[3];
    const float* bk = (const float*)d_in[4];
    const float* Wv = (const float*)d_in[5];
    const float* bv = (const float*)d_in[6];
    const float* Wo = (const float*)d_in[7];
    const float* bo = (const float*)d_in[8];
    float* out = (float*)d_out;

    __half *xc, *oc, *wc, *qh, *kh, *vh;
    cudaGetSymbolAddress((void**)&xc, g_Xc);
    cudaGetSymbolAddress((void**)&oc, g_Oc);
    cudaGetSymbolAddress((void**)&wc, g_Wc);
    cudaGetSymbolAddress((void**)&qh, g_Qh);
    cudaGetSymbolAddress((void**)&kh, g_Kh);
    cudaGetSymbolAddress((void**)&vh, g_Vh);

    prep_all<<<dim3(EMB / 32, EMB / 32, 5), dim3(32, 8)>>>(x, Wq, Wk, Wv, Wo, xc, wc);

    cudaFuncSetAttribute(gemm_qkv, cudaFuncAttributeMaxDynamicSharedMemorySize, GEMM_SMEM);
    cudaFuncSetAttribute(gemm_o,   cudaFuncAttributeMaxDynamicSharedMemorySize, GEMM_SMEM);

    gemm_qkv<<<dim3(EMB / 128, MTOT / 128, 3), 256, GEMM_SMEM>>>(
        xc, wc, bq, bk, bv, qh, kh, vh);

    cudaFuncSetAttribute(attn_mma, cudaFuncAttributeMaxDynamicSharedMemorySize, ATTN_SMEM);
    attn_mma<<<dim3(SEQ / 128, BHN), 256, ATTN_SMEM>>>();

    __half* wco = wc + (size_t)3 * EMB * KC2;
    gemm_o<<<dim3(EMB / 128, MTOT / 128), 256, GEMM_SMEM>>>(oc, wco, bo, out);
}

// round 16
// speedup vs baseline: 1.1794x; 1.1696x over previous
#include <cuda_runtime.h>
#include <cuda_fp16.h>
#include <cstdint>
#include <math.h>

#define EMB   768
#define HEADS 8
#define HD    96
#define BATCH 4
#define SEQ   2048
#define BHN   (BATCH*HEADS)
#define MTOT  (BATCH*SEQ)
#define LOG2E 1.4426950408889634f

// ---------------- scratch globals (module-load allocated) -------------------
__device__ __half g_Xh[(size_t)MTOT * EMB];    // x hi-only fp16
__device__ __half g_Oc[(size_t)MTOT * EMB];    // attn-out hi-only fp16
__device__ __half g_Wc[(size_t)4 * EMB * EMB]; // W^T fp16, stride 768: [Wq;Wk;Wv;Wo]
__device__ __half g_Qh[(size_t)BHN * SEQ * HD];
__device__ __half g_Kh[(size_t)BHN * SEQ * HD];
__device__ __half g_Vh[(size_t)BHN * SEQ * HD];

// ---------------- helpers ---------------------------------------------------
__device__ __forceinline__ uint32_t smem_u32(const void* p) {
    uint32_t a;
    asm("{ .reg .u64 t; cvta.to.shared.u64 t, %1; cvt.u32.u64 %0, t; }" : "=r"(a) : "l"(p));
    return a;
}
__device__ __forceinline__ void cpa16(uint32_t d, const void* s) {
    asm volatile("cp.async.cg.shared.global [%0], [%1], 16;" :: "r"(d), "l"(s));
}
#define CP_COMMIT() asm volatile("cp.async.commit_group;")
#define CP_WAIT0()  asm volatile("cp.async.wait_group 0;")
#define CP_WAIT1()  asm volatile("cp.async.wait_group 1;")

__device__ __forceinline__ void ldm4(uint32_t* r, uint32_t addr) {
    asm volatile("ldmatrix.sync.aligned.m8n8.x4.shared.b16 {%0,%1,%2,%3}, [%4];"
        : "=r"(r[0]), "=r"(r[1]), "=r"(r[2]), "=r"(r[3]) : "r"(addr));
}
__device__ __forceinline__ void ldm4t(uint32_t* r, uint32_t addr) {
    asm volatile("ldmatrix.sync.aligned.m8n8.x4.trans.shared.b16 {%0,%1,%2,%3}, [%4];"
        : "=r"(r[0]), "=r"(r[1]), "=r"(r[2]), "=r"(r[3]) : "r"(addr));
}
__device__ __forceinline__ void mma_f16(float* c, const uint32_t* a, uint32_t b0, uint32_t b1) {
    asm volatile("mma.sync.aligned.m16n8k16.row.col.f32.f16.f16.f32 "
        "{%0,%1,%2,%3}, {%4,%5,%6,%7}, {%8,%9}, {%0,%1,%2,%3};"
        : "+f"(c[0]), "+f"(c[1]), "+f"(c[2]), "+f"(c[3])
        : "r"(a[0]), "r"(a[1]), "r"(a[2]), "r"(a[3]), "r"(b0), "r"(b1));
}
// guaranteed-MUFU exp2
__device__ __forceinline__ float ex2f(float x) {
    float y;
    asm("ex2.approx.ftz.f32 %0, %1;" : "=f"(y) : "f"(x));
    return y;
}
// pack two fp32 -> fp16x2 {lo=x, hi=y} in one cvt
__device__ __forceinline__ uint32_t packh2(float x, float y) {
    uint32_t r;
    asm("cvt.rn.f16x2.f32 %0, %2, %1;" : "=r"(r) : "f"(x), "f"(y));
    return r;
}

// ===========================================================================
// fused prep: blockIdx.z 0..3 -> weight transpose (fp16, stride 768);
// z==4 -> x fp16 hi-only convert.
// ===========================================================================
__global__ void prep_all(const float* __restrict__ x,
                         const float* __restrict__ Wq, const float* __restrict__ Wk,
                         const float* __restrict__ Wv, const float* __restrict__ Wo,
                         __half* __restrict__ xh, __half* __restrict__ wc)
{
    __shared__ float t[32][33];
    const int z = blockIdx.z;
    const int tx = threadIdx.x, ty = threadIdx.y;

    if (z == 4) {
        const int tid = (blockIdx.y * 24 + blockIdx.x) * 256 + ty * 32 + tx;
        const int nthreads = 24 * 24 * 256;              // 147456
        for (int i = tid; i < MTOT * 192; i += nthreads) {
            const float4 v = ((const float4*)x)[i];
            __half h[4];
            h[0] = __float2half(v.x); h[1] = __float2half(v.y);
            h[2] = __float2half(v.z); h[3] = __float2half(v.w);
            *(uint2*)(xh + (size_t)i * 4) = *(uint2*)h;
        }
        return;
    }

    const float* W = (z == 0) ? Wq : (z == 1) ? Wk : (z == 2) ? Wv : Wo;
    __half* out = wc + (size_t)z * EMB * EMB;

    const int xg = blockIdx.x * 32 + tx;
    const int y0 = blockIdx.y * 32;
    #pragma unroll
    for (int i = ty; i < 32; i += 8)
        t[i][tx] = W[(size_t)(y0 + i) * EMB + xg];
    __syncthreads();
    #pragma unroll
    for (int i = ty; i < 32; i += 8) {
        const int n = blockIdx.x * 32 + i;
        const int k = y0 + tx;
        out[(size_t)n * EMB + k] = __float2half(t[tx][i]);
    }
}

// ===========================================================================
// shared GEMM core (128x128): k-chunk 64, SW128-xor swizzle, 3-stage.
// ===========================================================================
#define GSTAGE (256 * 128)                    // 32768 B per stage
#define GEMM_SMEM (3 * GSTAGE)                // 98304 B

__device__ __forceinline__ void gemm_core(
    const __half* __restrict__ A, const __half* __restrict__ B,
    int strideA, int strideB, int ktot, uint32_t sb,
    int tid, int wm, int wn, int midx, int lrow, int m0, int n0,
    float acc[4][4][4])
{
    auto load_chunk = [&](int c, int s) {
        const uint32_t base = sb + s * GSTAGE;
        #pragma unroll
        for (int t = 0; t < 8; t++) {
            const int idx = tid + t * 256;        // 0..2047
            const int row = idx >> 3, seg = idx & 7;
            const uint32_t dst = base + row * 128 + ((seg ^ (row & 7)) * 16);
            const __half* src = (row < 128)
                ? A + (size_t)(m0 + row) * strideA + c * 64 + seg * 8
                : B + (size_t)(n0 + row - 128) * strideB + c * 64 + seg * 8;
            cpa16(dst, src);
        }
    };

    auto compute = [&](int s) {
        const uint32_t base = sb + s * GSTAGE;
        #pragma unroll
        for (int kk8 = 0; kk8 < 8; kk8 += 2) {
            uint32_t af[4][4];
            const int sa = kk8 + (midx >> 1);
            #pragma unroll
            for (int mt = 0; mt < 4; mt++) {
                const int r = wm + mt * 16 + (midx & 1) * 8 + lrow;
                ldm4(af[mt], base + r * 128 + ((sa ^ (r & 7)) * 16));
            }
            const int sbg = kk8 + (midx & 1);
            #pragma unroll
            for (int np = 0; np < 2; np++) {
                uint32_t bf4[4];
                const int rb = wn + np * 16 + (midx >> 1) * 8 + lrow;
                ldm4(bf4, base + 16384 + rb * 128 + ((sbg ^ (rb & 7)) * 16));
                #pragma unroll
                for (int h2 = 0; h2 < 2; h2++) {
                    const int nt = np * 2 + h2;
                    #pragma unroll
                    for (int mt = 0; mt < 4; mt++)
                        mma_f16(acc[mt][nt], af[mt], bf4[h2 * 2], bf4[h2 * 2 + 1]);
                }
            }
        }
    };

    const int nch = ktot / 64;
    load_chunk(0, 0); CP_COMMIT();
    load_chunk(1, 1); CP_COMMIT();
    for (int c = 0; c < nch; c++) {
        CP_WAIT1();
        __syncthreads();
        if (c + 2 < nch) load_chunk(c + 2, (c + 2) % 3);
        CP_COMMIT();
        compute(c % 3);
    }
}

// ===========================================================================
// merged QKV projection: ONE GEMM, M=8192, N=2304 ([Wq;Wk;Wv] stacked),
// K=768, single fp16 product. Output/bias/scale selected by n0/768
// (uniform per CTA; 768 % 128 == 0). Q pre-scaled by log2(e).
// ===========================================================================
__global__ __launch_bounds__(256, 2) void gemm_qkv(
    const __half* __restrict__ A, const __half* __restrict__ wc,
    const float* __restrict__ bq, const float* __restrict__ bk,
    const float* __restrict__ bv,
    __half* __restrict__ qh, __half* __restrict__ kh, __half* __restrict__ vh)
{
    extern __shared__ __half gsm[];
    const uint32_t sbA = smem_u32(gsm);
    const int tid = threadIdx.x;
    const int wid = tid >> 5, lane = tid & 31;
    const int midx = lane >> 3, lrow = lane & 7;
    const int m0 = blockIdx.y * 128, n0 = blockIdx.x * 128;
    const int wm = (wid & 1) * 64, wn = (wid >> 1) * 32;

    const int z = n0 / EMB;                       // 0:Q 1:K 2:V (uniform)
    const int nloc0 = n0 - z * EMB;
    const float* bias = (z == 0) ? bq : (z == 1) ? bk : bv;
    __half* out0 = (z == 0) ? qh : (z == 1) ? kh : vh;
    const float scale = (z == 0) ? LOG2E : 1.0f;

    float acc[4][4][4];
    #pragma unroll
    for (int a = 0; a < 4; a++)
        #pragma unroll
        for (int b = 0; b < 4; b++)
            #pragma unroll
            for (int c = 0; c < 4; c++) acc[a][b][c] = 0.f;

    gemm_core(A, wc, EMB, EMB, EMB, sbA, tid, wm, wn, midx, lrow, m0, n0, acc);

    #pragma unroll
    for (int mt = 0; mt < 4; mt++) {
        #pragma unroll
        for (int nt = 0; nt < 4; nt++) {
            const int r  = wm + mt * 16 + (lane >> 2);
            const int cc = nloc0 + wn + nt * 8 + (lane & 3) * 2;  // within matrix
            #pragma unroll
            for (int half = 0; half < 2; half++) {       // rows r, r+8
                const int m = m0 + r + half * 8;
                const float v0 = (acc[mt][nt][half * 2]     + bias[cc])     * scale;
                const float v1 = (acc[mt][nt][half * 2 + 1] + bias[cc + 1]) * scale;
                const int bb = m >> 11, nn = m & (SEQ - 1);
                const int h = cc / HD, d = cc % HD;       // pair stays in one head
                const size_t i0 = ((size_t)(bb * HEADS + h) * SEQ + nn) * HD + d;
                *(uint32_t*)(out0 + i0) = packh2(v0, v1);
            }
        }
    }
}

// ===========================================================================
// output projection (128x128 tile): K=768 single product, fp32 [m][768]
// ===========================================================================
__global__ __launch_bounds__(256, 2) void gemm_o(
    const __half* __restrict__ A, const __half* __restrict__ B,
    const float* __restrict__ bias, float* __restrict__ outf)
{
    extern __shared__ __half gsm[];
    const uint32_t sbA = smem_u32(gsm);
    const int tid = threadIdx.x;
    const int wid = tid >> 5, lane = tid & 31;
    const int midx = lane >> 3, lrow = lane & 7;
    const int m0 = blockIdx.y * 128, n0 = blockIdx.x * 128;
    const int wm = (wid & 1) * 64, wn = (wid >> 1) * 32;

    float acc[4][4][4];
    #pragma unroll
    for (int a = 0; a < 4; a++)
        #pragma unroll
        for (int b = 0; b < 4; b++)
            #pragma unroll
            for (int c = 0; c < 4; c++) acc[a][b][c] = 0.f;

    gemm_core(A, B, EMB, EMB, EMB, sbA, tid, wm, wn, midx, lrow, m0, n0, acc);

    #pragma unroll
    for (int mt = 0; mt < 4; mt++) {
        #pragma unroll
        for (int nt = 0; nt < 4; nt++) {
            const int r  = wm + mt * 16 + (lane >> 2);
            const int cc = n0 + wn + nt * 8 + (lane & 3) * 2;
            #pragma unroll
            for (int half = 0; half < 2; half++) {
                const int m = m0 + r + half * 8;
                *(float2*)(outf + (size_t)m * EMB + cc) = make_float2(
                    acc[mt][nt][half * 2] + bias[cc],
                    acc[mt][nt][half * 2 + 1] + bias[cc + 1]);
            }
        }
    }
}

// ===========================================================================
// Flash attention (R10 schedule): S = qh·kh, PV single-product, MUFU exp2,
// split-phase K/V prefetch, conditional oacc rescale, lane-partial l.
// ===========================================================================
#define APAD 104
#define ATTN_SMEM ((128 + 2 * 64) * APAD * 2)            // 53248 B

__global__ __launch_bounds__(256, 2) void attn_mma()
{
    extern __shared__ __half asmem[];
    const uint32_t sQh = smem_u32(asmem);
    const uint32_t sKh = sQh + 128 * APAD * 2;
    const uint32_t sVh = sKh + 64 * APAD * 2;

    const int tid = threadIdx.x;
    const int wid = tid >> 5, lane = tid & 31;
    const int midx = lane >> 3, lrow = lane & 7;
    const int q0 = blockIdx.x * 128;
    const int bh = blockIdx.y;

    const __half* bQh = g_Qh + (size_t)bh * SEQ * HD;
    const __half* bKh = g_Kh + (size_t)bh * SEQ * HD;
    const __half* bVh = g_Vh + (size_t)bh * SEQ * HD;

    auto loadK = [&](int kt) {
        #pragma unroll
        for (int t = 0; t < 3; t++) {
            const int i = tid + t * 256;                 // < 768
            const int r = i / 12, seg = i % 12;
            cpa16(sKh + (r * APAD + seg * 8) * 2, bKh + (size_t)(kt * 64 + r) * HD + seg * 8);
        }
    };
    auto loadV = [&](int kt) {
        #pragma unroll
        for (int t = 0; t < 3; t++) {
            const int i = tid + t * 256;                 // < 768
            const int r = i / 12, seg = i % 12;
            cpa16(sVh + (r * APAD + seg * 8) * 2, bVh + (size_t)(kt * 64 + r) * HD + seg * 8);
        }
    };

    // prologue: Q + K0 in group 0, V0 in group 1
    #pragma unroll
    for (int t = 0; t < 6; t++) {
        const int i = tid + t * 256;                     // < 1536
        const int r = i / 12, seg = i % 12;
        cpa16(sQh + (r * APAD + seg * 8) * 2, bQh + (size_t)(q0 + r) * HD + seg * 8);
    }
    loadK(0);
    CP_COMMIT();
    loadV(0);
    CP_COMMIT();

    float m0v = -INFINITY, m1v = -INFINITY, l0 = 0.f, l1 = 0.f;  // l: lane-partial
    float oacc[12][4];
    #pragma unroll
    for (int d = 0; d < 12; d++)
        #pragma unroll
        for (int c = 0; c < 4; c++) oacc[d][c] = 0.f;

    const int NT = SEQ / 64;
    for (int kt = 0; kt < NT; kt++) {
        CP_WAIT1();                      // K(kt) (+Q on first iter) ready
        __syncthreads();

        // ---- S (log2-space) = Qh Kh^T, single product ----
        float sacc[8][4];
        #pragma unroll
        for (int n = 0; n < 8; n++)
            #pragma unroll
            for (int c = 0; c < 4; c++) sacc[n][c] = 0.f;

        #pragma unroll
        for (int kd = 0; kd < HD; kd += 16) {
            uint32_t qh4[4];
            const uint32_t qoff =
                ((wid * 16 + (midx & 1) * 8 + lrow) * APAD + kd + (midx >> 1) * 8) * 2;
            ldm4(qh4, sQh + qoff);
            #pragma unroll
            for (int np = 0; np < 4; np++) {
                uint32_t kh4[4];
                const uint32_t koff =
                    ((np * 16 + (midx >> 1) * 8 + lrow) * APAD + kd + (midx & 1) * 8) * 2;
                ldm4(kh4, sKh + koff);
                #pragma unroll
                for (int h2 = 0; h2 < 2; h2++)
                    mma_f16(sacc[np * 2 + h2], qh4, kh4[h2 * 2], kh4[h2 * 2 + 1]);
            }
        }

        __syncthreads();                 // all warps done reading K buffer
        if (kt + 1 < NT) loadK(kt + 1);  // overlaps softmax + PV below
        CP_COMMIT();

        // ---- online softmax in log2 space (MUFU ex2; 4-lane row groups) ----
        float mx0 = -INFINITY, mx1 = -INFINITY;
        #pragma unroll
        for (int n = 0; n < 8; n++) {
            mx0 = fmaxf(mx0, fmaxf(sacc[n][0], sacc[n][1]));
            mx1 = fmaxf(mx1, fmaxf(sacc[n][2], sacc[n][3]));
        }
        mx0 = fmaxf(mx0, __shfl_xor_sync(0xffffffffu, mx0, 1));
        mx0 = fmaxf(mx0, __shfl_xor_sync(0xffffffffu, mx0, 2));
        mx1 = fmaxf(mx1, __shfl_xor_sync(0xffffffffu, mx1, 1));
        mx1 = fmaxf(mx1, __shfl_xor_sync(0xffffffffu, mx1, 2));

        const float mn0 = fmaxf(m0v, mx0), a0v = ex2f(m0v - mn0);
        const float mn1 = fmaxf(m1v, mx1), a1v = ex2f(m1v - mn1);
        m0v = mn0; m1v = mn1;

        float rs0 = 0.f, rs1 = 0.f;      // this lane's 16-value partial sums
        #pragma unroll
        for (int n = 0; n < 8; n++) {
            sacc[n][0] = ex2f(sacc[n][0] - mn0); rs0 += sacc[n][0];
            sacc[n][1] = ex2f(sacc[n][1] - mn0); rs0 += sacc[n][1];
            sacc[n][2] = ex2f(sacc[n][2] - mn1); rs1 += sacc[n][2];
            sacc[n][3] = ex2f(sacc[n][3] - mn1); rs1 += sacc[n][3];
        }
        l0 = l0 * a0v + rs0;
        l1 = l1 * a1v + rs1;

        // rescale only when the running max actually moved (alpha < 1)
        if (a0v != 1.f || a1v != 1.f) {
            #pragma unroll
            for (int d = 0; d < 12; d++) {
                oacc[d][0] *= a0v; oacc[d][1] *= a0v;
                oacc[d][2] *= a1v; oacc[d][3] *= a1v;
            }
        }

        CP_WAIT1();                      // V(kt) ready (K(kt+1) still in flight)
        __syncthreads();

        // ---- O += P V  (single fp16 product; P packed via one cvt) ----
        #pragma unroll
        for (int st = 0; st < 4; st++) {
            uint32_t ph[4];
            ph[0] = packh2(sacc[2*st][0],   sacc[2*st][1]);
            ph[1] = packh2(sacc[2*st][2],   sacc[2*st][3]);
            ph[2] = packh2(sacc[2*st+1][0], sacc[2*st+1][1]);
            ph[3] = packh2(sacc[2*st+1][2], sacc[2*st+1][3]);
            #pragma unroll
            for (int dp = 0; dp < 6; dp++) {
                uint32_t vh4[4];
                const uint32_t voff =
                    ((st * 16 + (midx & 1) * 8 + lrow) * APAD + dp * 16 + (midx >> 1) * 8) * 2;
                ldm4t(vh4, sVh + voff);
                mma_f16(oacc[dp*2],   ph, vh4[0], vh4[1]);
                mma_f16(oacc[dp*2+1], ph, vh4[2], vh4[3]);
            }
        }

        __syncthreads();                 // all warps done reading V buffer
        if (kt + 1 < NT) loadV(kt + 1);  // overlaps next S-phase
        CP_COMMIT();
    }

    // finalize lane-partial denominators (one cross-lane reduction total)
    l0 += __shfl_xor_sync(0xffffffffu, l0, 1);
    l0 += __shfl_xor_sync(0xffffffffu, l0, 2);
    l1 += __shfl_xor_sync(0xffffffffu, l1, 1);
    l1 += __shfl_xor_sync(0xffffffffu, l1, 2);

    // epilogue: /(l*sqrt(96)), hi-only fp16 into O-projection operand
    const float inv0 = 0.10206207261596577f / l0;
    const float inv1 = 0.10206207261596577f / l1;
    const int bb = bh >> 3, h = bh & 7;
    const int row0 = q0 + wid * 16 + (lane >> 2);
    __half* o0 = g_Oc + (size_t)(bb * SEQ + row0) * EMB + h * HD + (lane & 3) * 2;
    __half* o1 = o0 + (size_t)8 * EMB;
    #pragma unroll
    for (int dp = 0; dp < 12; dp++) {
        *(uint32_t*)(o0 + dp * 8) = packh2(oacc[dp][0] * inv0, oacc[dp][1] * inv0);
        *(uint32_t*)(o1 + dp * 8) = packh2(oacc[dp][2] * inv1, oacc[dp][3] * inv1);
    }
}

// ---------------------------------------------------------------------------
extern "C" void kernel_launch(void* const* d_in, const int* in_sizes, int n_in,
                              void* d_out, int out_size)
{
    const float* x  = (const float*)d_in[0];
    const float* Wq = (const float*)d_in[1];
    const float* bq = (const float*)d_in[2];
    const float* Wk = (const float*)d_in[3];
    const float* bk = (const float*)d_in[4];
    const float* Wv = (const float*)d_in[5];
    const float* bv = (const float*)d_in[6];
    const float* Wo = (const float*)d_in[7];
    const float* bo = (const float*)d_in[8];
    float* out = (float*)d_out;

    __half *xh, *oc, *wc, *qh, *kh, *vh;
    cudaGetSymbolAddress((void**)&xh, g_Xh);
    cudaGetSymbolAddress((void**)&oc, g_Oc);
    cudaGetSymbolAddress((void**)&wc, g_Wc);
    cudaGetSymbolAddress((void**)&qh, g_Qh);
    cudaGetSymbolAddress((void**)&kh, g_Kh);
    cudaGetSymbolAddress((void**)&vh, g_Vh);

    prep_all<<<dim3(EMB / 32, EMB / 32, 5), dim3(32, 8)>>>(x, Wq, Wk, Wv, Wo, xh, wc);

    cudaFuncSetAttribute(gemm_qkv, cudaFuncAttributeMaxDynamicSharedMemorySize, GEMM_SMEM);
    cudaFuncSetAttribute(gemm_o,   cudaFuncAttributeMaxDynamicSharedMemorySize, GEMM_SMEM);

    gemm_qkv<<<dim3(3 * EMB / 128, MTOT / 128), 256, GEMM_SMEM>>>(
        xh, wc, bq, bk, bv, qh, kh, vh);

    cudaFuncSetAttribute(attn_mma, cudaFuncAttributeMaxDynamicSharedMemorySize, ATTN_SMEM);
    attn_mma<<<dim3(SEQ / 128, BHN), 256, ATTN_SMEM>>>();

    __half* wco = wc + (size_t)3 * EMB * EMB;
    gemm_o<<<dim3(EMB / 128, MTOT / 128), 256, GEMM_SMEM>>>(oc, wco, bo, out);
}